// round 3
// baseline (speedup 1.0000x reference)
#include <cuda_runtime.h>
#include <math.h>

// Problem constants
#define B_   8
#define C_   64
#define HW_  4096      // 64*64 tokens
#define PAD  68        // row stride in floats (64 + 4), keeps 16B alignment, breaks bank conflicts

// Scratch (allocation-free rule: __device__ globals)
__device__ float g_Q[B_ * HW_ * C_];
__device__ float g_K[B_ * HW_ * C_];
__device__ float g_V[B_ * HW_ * C_];
__device__ float g_O[B_ * HW_ * C_];

// ---------------------------------------------------------------------------
// Kernel 1: Q/K/V projections.  q[b,n,d] = sum_c x[b,c,n] * wq[d,c] + bq[d]
// Grid: (64 token-tiles, 8 batches), 256 threads.
// ---------------------------------------------------------------------------
__global__ void proj_kernel(const float* __restrict__ x,
                            const float* __restrict__ wq, const float* __restrict__ bq,
                            const float* __restrict__ wk, const float* __restrict__ bk,
                            const float* __restrict__ wv, const float* __restrict__ bv)
{
    extern __shared__ float sm[];
    float* xs  = sm;                 // [64 tokens][PAD] token-major: xs[n][c]
    float* wqs = xs  + 64 * PAD;     // [64 d][PAD c]
    float* wks = wqs + 64 * PAD;
    float* wvs = wks + 64 * PAD;

    const int b  = blockIdx.y;
    const int n0 = blockIdx.x * 64;
    const int t  = threadIdx.x;

    const float* xb = x + (size_t)b * C_ * HW_;
    // Load x tile, transposing [c][n] -> [n][c]. Global reads coalesced over n.
    for (int idx = t; idx < 64 * 64; idx += 256) {
        int c = idx >> 6, n = idx & 63;
        xs[n * PAD + c] = xb[c * HW_ + n0 + n];
    }
    // Load weights [d][c]
    for (int idx = t; idx < 64 * 64; idx += 256) {
        int d = idx >> 6, c = idx & 63;
        wqs[d * PAD + c] = wq[idx];
        wks[d * PAD + c] = wk[idx];
        wvs[d * PAD + c] = wv[idx];
    }
    __syncthreads();

    // Thread t: token n = t/4, channel block d0 = (t%4)*16
    const int n  = t >> 2;
    const int d0 = (t & 3) * 16;

    float aq[16], ak[16], av[16];
    #pragma unroll
    for (int j = 0; j < 16; j++) {
        aq[j] = bq[d0 + j];
        ak[j] = bk[d0 + j];
        av[j] = bv[d0 + j];
    }

    for (int c = 0; c < 64; c += 4) {
        float4 xv = *(const float4*)&xs[n * PAD + c];
        #pragma unroll
        for (int j = 0; j < 16; j++) {
            float4 wv4;
            wv4 = *(const float4*)&wqs[(d0 + j) * PAD + c];
            aq[j] += xv.x * wv4.x + xv.y * wv4.y + xv.z * wv4.z + xv.w * wv4.w;
            wv4 = *(const float4*)&wks[(d0 + j) * PAD + c];
            ak[j] += xv.x * wv4.x + xv.y * wv4.y + xv.z * wv4.z + xv.w * wv4.w;
            wv4 = *(const float4*)&wvs[(d0 + j) * PAD + c];
            av[j] += xv.x * wv4.x + xv.y * wv4.y + xv.z * wv4.z + xv.w * wv4.w;
        }
    }

    float* qg = g_Q + ((size_t)b * HW_ + n0 + n) * C_ + d0;
    float* kg = g_K + ((size_t)b * HW_ + n0 + n) * C_ + d0;
    float* vg = g_V + ((size_t)b * HW_ + n0 + n) * C_ + d0;
    #pragma unroll
    for (int j = 0; j < 16; j += 4) {
        *(float4*)&qg[j] = make_float4(aq[j], aq[j+1], aq[j+2], aq[j+3]);
        *(float4*)&kg[j] = make_float4(ak[j], ak[j+1], ak[j+2], ak[j+3]);
        *(float4*)&vg[j] = make_float4(av[j], av[j+1], av[j+2], av[j+3]);
    }
}

// ---------------------------------------------------------------------------
// Kernel 2: flash attention per 64-query tile with online softmax.
// Grid: (64 q-tiles, 8 batches), 256 threads.
// Thread t owns query q = t/4 and O channels [ (t%4)*16 , +16 ).
// ---------------------------------------------------------------------------
__global__ void attn_kernel()
{
    extern __shared__ float sm[];
    float* Qs = sm;               // [64][PAD]  (pre-scaled by 1/sqrt(C))
    float* Ks = Qs + 64 * PAD;
    float* Vs = Ks + 64 * PAD;
    float* Ss = Vs + 64 * PAD;    // softmax probs [64 q][PAD kk]

    const int b  = blockIdx.y;
    const int qt = blockIdx.x;
    const int t  = threadIdx.x;

    const float* Qg = g_Q + ((size_t)b * HW_ + qt * 64) * C_;
    for (int idx = t; idx < 64 * 64; idx += 256) {
        int n = idx >> 6, c = idx & 63;
        Qs[n * PAD + c] = Qg[idx] * 0.125f;   // fold 1/sqrt(64) into Q
    }

    const int q  = t >> 2;
    const int g4 = t & 3;
    const int d0 = g4 * 16;
    const int k0 = g4 * 16;

    float m = -INFINITY, l = 0.0f;
    float acc[16];
    #pragma unroll
    for (int j = 0; j < 16; j++) acc[j] = 0.0f;

    const float* Kb = g_K + (size_t)b * HW_ * C_;
    const float* Vb = g_V + (size_t)b * HW_ * C_;
    __syncthreads();

    for (int kt = 0; kt < 64; kt++) {
        const float* Kg = Kb + kt * 64 * C_;
        const float* Vg = Vb + kt * 64 * C_;
        for (int idx = t; idx < 64 * 64; idx += 256) {
            int n = idx >> 6, c = idx & 63;
            Ks[n * PAD + c] = Kg[idx];
            Vs[n * PAD + c] = Vg[idx];
        }
        __syncthreads();

        // ---- S = Q @ K^T for my (q, 16 kk's) ----
        float sv[16];
        #pragma unroll
        for (int j = 0; j < 16; j++) sv[j] = 0.0f;
        for (int c = 0; c < 64; c += 4) {
            float4 qv = *(const float4*)&Qs[q * PAD + c];
            #pragma unroll
            for (int j = 0; j < 16; j++) {
                float4 kv = *(const float4*)&Ks[(k0 + j) * PAD + c];
                sv[j] += qv.x * kv.x + qv.y * kv.y + qv.z * kv.z + qv.w * kv.w;
            }
        }

        // ---- online softmax update for row q (group of 4 lanes) ----
        float rmax = -INFINITY;
        #pragma unroll
        for (int j = 0; j < 16; j++) rmax = fmaxf(rmax, sv[j]);
        rmax = fmaxf(rmax, __shfl_xor_sync(0xffffffffu, rmax, 1));
        rmax = fmaxf(rmax, __shfl_xor_sync(0xffffffffu, rmax, 2));

        float newm  = fmaxf(m, rmax);
        float alpha = __expf(m - newm);
        float psum  = 0.0f;
        #pragma unroll
        for (int j = 0; j < 16; j++) {
            float p = __expf(sv[j] - newm);
            Ss[q * PAD + k0 + j] = p;
            psum += p;
        }
        psum += __shfl_xor_sync(0xffffffffu, psum, 1);
        psum += __shfl_xor_sync(0xffffffffu, psum, 2);

        l = l * alpha + psum;
        m = newm;
        #pragma unroll
        for (int j = 0; j < 16; j++) acc[j] *= alpha;
        __syncthreads();   // Ss visible to all 4 lanes of each q-group

        // ---- O += P @ V (my 16 channels) ----
        for (int kk = 0; kk < 64; kk++) {
            float p = Ss[q * PAD + kk];
            const float* vr = &Vs[kk * PAD + d0];
            float4 v0 = *(const float4*)&vr[0];
            float4 v1 = *(const float4*)&vr[4];
            float4 v2 = *(const float4*)&vr[8];
            float4 v3 = *(const float4*)&vr[12];
            acc[0]  += p * v0.x; acc[1]  += p * v0.y; acc[2]  += p * v0.z; acc[3]  += p * v0.w;
            acc[4]  += p * v1.x; acc[5]  += p * v1.y; acc[6]  += p * v1.z; acc[7]  += p * v1.w;
            acc[8]  += p * v2.x; acc[9]  += p * v2.y; acc[10] += p * v2.z; acc[11] += p * v2.w;
            acc[12] += p * v3.x; acc[13] += p * v3.y; acc[14] += p * v3.z; acc[15] += p * v3.w;
        }
        __syncthreads();   // safe to overwrite Ks/Vs/Ss next iter
    }

    const float inv = 1.0f / l;
    float* og = g_O + ((size_t)b * HW_ + qt * 64 + q) * C_ + d0;
    #pragma unroll
    for (int j = 0; j < 16; j += 4)
        *(float4*)&og[j] = make_float4(acc[j] * inv, acc[j+1] * inv, acc[j+2] * inv, acc[j+3] * inv);
}

// ---------------------------------------------------------------------------
// Kernel 3: mixed = relu(O @ wm^T + bm), then exact 2x2 average pool
// (bilinear 64->32 half-pixel == avg pool), write [B,C,32,32].
// Grid: (32 output rows, 8 batches), 256 threads.
// ---------------------------------------------------------------------------
__global__ void mixpool_kernel(const float* __restrict__ wm,
                               const float* __restrict__ bm,
                               float* __restrict__ out)
{
    extern __shared__ float sm[];
    float* Os  = sm;                // [128 tokens][PAD]  (input rows 2*oy, 2*oy+1)
    float* wms = Os + 128 * PAD;    // [64 d][PAD c]

    const int b  = blockIdx.y;
    const int oy = blockIdx.x;
    const int t  = threadIdx.x;

    const float* Og = g_O + ((size_t)b * HW_ + oy * 2 * 64) * C_;
    for (int idx = t; idx < 128 * 64; idx += 256) {
        int n = idx >> 6, c = idx & 63;
        Os[n * PAD + c] = Og[idx];
    }
    for (int idx = t; idx < 64 * 64; idx += 256) {
        int d = idx >> 6, c = idx & 63;
        wms[d * PAD + c] = wm[idx];
    }
    __syncthreads();

    #pragma unroll
    for (int k = 0; k < 8; k++) {
        int oidx = t + k * 256;        // 0..2047 = (channel, ox)
        int ch   = oidx >> 5;
        int ox   = oidx & 31;
        float bias = bm[ch];
        float s = 0.0f;
        #pragma unroll
        for (int dy = 0; dy < 2; dy++) {
            #pragma unroll
            for (int dx = 0; dx < 2; dx++) {
                int tl = dy * 64 + ox * 2 + dx;     // local token row
                float a = bias;
                for (int c = 0; c < 64; c += 4) {
                    float4 ov = *(const float4*)&Os[tl * PAD + c];
                    float4 wv = *(const float4*)&wms[ch * PAD + c];
                    a += ov.x * wv.x + ov.y * wv.y + ov.z * wv.z + ov.w * wv.w;
                }
                s += fmaxf(a, 0.0f);
            }
        }
        out[(((size_t)b * C_ + ch) * 32 + oy) * 32 + ox] = 0.25f * s;
    }
}

// ---------------------------------------------------------------------------
extern "C" void kernel_launch(void* const* d_in, const int* in_sizes, int n_in,
                              void* d_out, int out_size)
{
    const float* x  = (const float*)d_in[0];
    const float* wq = (const float*)d_in[1];
    const float* bq = (const float*)d_in[2];
    const float* wk = (const float*)d_in[3];
    const float* bk = (const float*)d_in[4];
    const float* wv = (const float*)d_in[5];
    const float* bv = (const float*)d_in[6];
    const float* wm = (const float*)d_in[7];
    const float* bm = (const float*)d_in[8];
    float* out = (float*)d_out;

    const int smem_proj = 4 * 64 * PAD * sizeof(float);            // 69632
    const int smem_attn = 4 * 64 * PAD * sizeof(float);            // 69632
    const int smem_mix  = (128 + 64) * PAD * sizeof(float);        // 52224

    cudaFuncSetAttribute(proj_kernel,    cudaFuncAttributeMaxDynamicSharedMemorySize, smem_proj);
    cudaFuncSetAttribute(attn_kernel,    cudaFuncAttributeMaxDynamicSharedMemorySize, smem_attn);
    cudaFuncSetAttribute(mixpool_kernel, cudaFuncAttributeMaxDynamicSharedMemorySize, smem_mix);

    proj_kernel<<<dim3(64, B_), 256, smem_proj>>>(x, wq, bq, wk, bk, wv, bv);
    attn_kernel<<<dim3(64, B_), 256, smem_attn>>>();
    mixpool_kernel<<<dim3(32, B_), 256, smem_mix>>>(wm, bm, out);
}

// round 4
// speedup vs baseline: 11.5708x; 11.5708x over previous
#include <cuda_runtime.h>
#include <cuda_bf16.h>
#include <math.h>
#include <stdint.h>

// Problem constants
#define B_   8
#define C_   64
#define HW_  4096      // 64*64 tokens
#define PAD  68        // proj/mixpool smem row stride

// Scratch (allocation-free rule: __device__ globals)
__device__ float g_Q[B_ * HW_ * C_];
__device__ float g_K[B_ * HW_ * C_];
__device__ float g_V[B_ * HW_ * C_];
__device__ float g_O[B_ * HW_ * C_];

// ---------------------------------------------------------------------------
// Kernel 1: Q/K/V projections (unchanged from R3 — known good).
// ---------------------------------------------------------------------------
__global__ void proj_kernel(const float* __restrict__ x,
                            const float* __restrict__ wq, const float* __restrict__ bq,
                            const float* __restrict__ wk, const float* __restrict__ bk,
                            const float* __restrict__ wv, const float* __restrict__ bv)
{
    extern __shared__ float sm[];
    float* xs  = sm;
    float* wqs = xs  + 64 * PAD;
    float* wks = wqs + 64 * PAD;
    float* wvs = wks + 64 * PAD;

    const int b  = blockIdx.y;
    const int n0 = blockIdx.x * 64;
    const int t  = threadIdx.x;

    const float* xb = x + (size_t)b * C_ * HW_;
    for (int idx = t; idx < 64 * 64; idx += 256) {
        int c = idx >> 6, n = idx & 63;
        xs[n * PAD + c] = xb[c * HW_ + n0 + n];
    }
    for (int idx = t; idx < 64 * 64; idx += 256) {
        int d = idx >> 6, c = idx & 63;
        wqs[d * PAD + c] = wq[idx];
        wks[d * PAD + c] = wk[idx];
        wvs[d * PAD + c] = wv[idx];
    }
    __syncthreads();

    const int n  = t >> 2;
    const int d0 = (t & 3) * 16;

    float aq[16], ak[16], av[16];
    #pragma unroll
    for (int j = 0; j < 16; j++) {
        aq[j] = bq[d0 + j];
        ak[j] = bk[d0 + j];
        av[j] = bv[d0 + j];
    }

    for (int c = 0; c < 64; c += 4) {
        float4 xv = *(const float4*)&xs[n * PAD + c];
        #pragma unroll
        for (int j = 0; j < 16; j++) {
            float4 wv4;
            wv4 = *(const float4*)&wqs[(d0 + j) * PAD + c];
            aq[j] += xv.x * wv4.x + xv.y * wv4.y + xv.z * wv4.z + xv.w * wv4.w;
            wv4 = *(const float4*)&wks[(d0 + j) * PAD + c];
            ak[j] += xv.x * wv4.x + xv.y * wv4.y + xv.z * wv4.z + xv.w * wv4.w;
            wv4 = *(const float4*)&wvs[(d0 + j) * PAD + c];
            av[j] += xv.x * wv4.x + xv.y * wv4.y + xv.z * wv4.z + xv.w * wv4.w;
        }
    }

    float* qg = g_Q + ((size_t)b * HW_ + n0 + n) * C_ + d0;
    float* kg = g_K + ((size_t)b * HW_ + n0 + n) * C_ + d0;
    float* vg = g_V + ((size_t)b * HW_ + n0 + n) * C_ + d0;
    #pragma unroll
    for (int j = 0; j < 16; j += 4) {
        *(float4*)&qg[j] = make_float4(aq[j], aq[j+1], aq[j+2], aq[j+3]);
        *(float4*)&kg[j] = make_float4(ak[j], ak[j+1], ak[j+2], ak[j+3]);
        *(float4*)&vg[j] = make_float4(av[j], av[j+1], av[j+2], av[j+3]);
    }
}

// ---------------------------------------------------------------------------
// Tensor-core flash attention (bf16 split-precision mma.sync).
// CTA: 128 queries, 8 warps; warp owns 16 query rows. Key chunks of 64.
// S = Q K^T via 3-term bf16 split (QhiKhi + QhiKlo + QloKhi) — fp32-grade.
// P fragments: m16n8 C-layout == m16k16 A-layout, so PV needs no staging.
// ---------------------------------------------------------------------------
// smem (uint32 words, single buffer):
//   khi[key*36 + cp]  key<64, cp<32 (bf16x2 pair along c)   : 2304 words
//   klo               +2304
//   vhi[kp*72 + ch]   kp<32, ch<64 (bf16x2 pair along keys) : 2304 words
//   vlo               +2304
#define SM_KHI 0
#define SM_KLO 2304
#define SM_VHI 4608
#define SM_VLO 6912
#define SM_WORDS 9216

__device__ __forceinline__ void bsplit2(float x, float y, uint32_t& hi, uint32_t& lo)
{
    __nv_bfloat162 h = __floats2bfloat162_rn(x, y);
    float2 hf = __bfloat1622float2(h);
    __nv_bfloat162 l = __floats2bfloat162_rn(x - hf.x, y - hf.y);
    hi = *reinterpret_cast<uint32_t*>(&h);
    lo = *reinterpret_cast<uint32_t*>(&l);
}

__device__ __forceinline__ void mma_bf16(float* d, const uint32_t* a, uint32_t b0, uint32_t b1)
{
    asm volatile(
        "mma.sync.aligned.m16n8k16.row.col.f32.bf16.bf16.f32 "
        "{%0,%1,%2,%3}, {%4,%5,%6,%7}, {%8,%9}, {%0,%1,%2,%3};\n"
        : "+f"(d[0]), "+f"(d[1]), "+f"(d[2]), "+f"(d[3])
        : "r"(a[0]), "r"(a[1]), "r"(a[2]), "r"(a[3]), "r"(b0), "r"(b1));
}

__global__ __launch_bounds__(256, 2) void attn_kernel()
{
    extern __shared__ uint32_t sw[];

    const int b    = blockIdx.y;
    const int qt   = blockIdx.x;        // 32 tiles of 128 queries
    const int t    = threadIdx.x;
    const int w    = t >> 5;
    const int lane = t & 31;
    const int g    = lane >> 2;         // groupID (row within fragment)
    const int tg   = lane & 3;          // thread-in-group (col pair)

    // ---- Q fragments (persistent): A-frags for 4 k-steps, hi+lo split ----
    uint32_t Ahi[4][4], Alo[4][4];
    {
        const float* Qg = g_Q + ((size_t)b * HW_ + qt * 128 + w * 16) * C_;
        #pragma unroll
        for (int ks = 0; ks < 4; ks++) {
            int cb = ks * 16 + 2 * tg;
            float2 q00 = *(const float2*)&Qg[g * 64 + cb];
            float2 q10 = *(const float2*)&Qg[(g + 8) * 64 + cb];
            float2 q01 = *(const float2*)&Qg[g * 64 + cb + 8];
            float2 q11 = *(const float2*)&Qg[(g + 8) * 64 + cb + 8];
            // fold softmax scale 1/sqrt(64) into Q
            bsplit2(q00.x * 0.125f, q00.y * 0.125f, Ahi[ks][0], Alo[ks][0]);
            bsplit2(q10.x * 0.125f, q10.y * 0.125f, Ahi[ks][1], Alo[ks][1]);
            bsplit2(q01.x * 0.125f, q01.y * 0.125f, Ahi[ks][2], Alo[ks][2]);
            bsplit2(q11.x * 0.125f, q11.y * 0.125f, Ahi[ks][3], Alo[ks][3]);
        }
    }

    float O[32];
    #pragma unroll
    for (int j = 0; j < 32; j++) O[j] = 0.0f;
    float m0 = -1e30f, m1 = -1e30f, l0 = 0.0f, l1 = 0.0f;

    const float* Kb = g_K + (size_t)b * HW_ * C_;
    const float* Vb = g_V + (size_t)b * HW_ * C_;

    for (int kt = 0; kt < 64; kt++) {
        __syncthreads();   // previous chunk's compute done before overwrite
        const float* Kg = Kb + kt * 64 * C_;
        const float* Vg = Vb + kt * 64 * C_;

        // K: [key][c] -> bf16x2 pairs along c. 2048 words, 8 per thread.
        #pragma unroll
        for (int i = 0; i < 8; i++) {
            int idx = t + i * 256;
            int key = idx >> 5, cp = idx & 31;
            float2 kv = *(const float2*)&Kg[key * 64 + 2 * cp];
            uint32_t h, l;
            bsplit2(kv.x, kv.y, h, l);
            sw[SM_KHI + key * 36 + cp] = h;
            sw[SM_KLO + key * 36 + cp] = l;
        }
        // V: transpose to [keypair][ch], pairs along keys. Coalesced over ch.
        #pragma unroll
        for (int i = 0; i < 8; i++) {
            int idx = t + i * 256;
            int ch = idx & 63, kp = idx >> 6;
            float v0 = Vg[(2 * kp) * 64 + ch];
            float v1 = Vg[(2 * kp + 1) * 64 + ch];
            uint32_t h, l;
            bsplit2(v0, v1, h, l);
            sw[SM_VHI + kp * 72 + ch] = h;
            sw[SM_VLO + kp * 72 + ch] = l;
        }
        __syncthreads();

        // ---- S = Q @ K^T  (16 x 64 per warp) ----
        float Sv[32];
        #pragma unroll
        for (int j = 0; j < 32; j++) Sv[j] = 0.0f;

        #pragma unroll
        for (int ks = 0; ks < 4; ks++) {
            #pragma unroll
            for (int n = 0; n < 8; n++) {
                uint32_t base = (uint32_t)(n * 8 + g) * 36 + tg + ks * 8;
                uint32_t bh0 = sw[SM_KHI + base];
                uint32_t bh1 = sw[SM_KHI + base + 4];
                uint32_t bl0 = sw[SM_KLO + base];
                uint32_t bl1 = sw[SM_KLO + base + 4];
                float* d = &Sv[n * 4];
                mma_bf16(d, Ahi[ks], bh0, bh1);
                mma_bf16(d, Ahi[ks], bl0, bl1);
                mma_bf16(d, Alo[ks], bh0, bh1);
            }
        }

        // ---- online softmax (rows g and g+8) ----
        float rm0 = -1e30f, rm1 = -1e30f;
        #pragma unroll
        for (int n = 0; n < 8; n++) {
            rm0 = fmaxf(rm0, fmaxf(Sv[n * 4 + 0], Sv[n * 4 + 1]));
            rm1 = fmaxf(rm1, fmaxf(Sv[n * 4 + 2], Sv[n * 4 + 3]));
        }
        rm0 = fmaxf(rm0, __shfl_xor_sync(0xffffffffu, rm0, 1));
        rm0 = fmaxf(rm0, __shfl_xor_sync(0xffffffffu, rm0, 2));
        rm1 = fmaxf(rm1, __shfl_xor_sync(0xffffffffu, rm1, 1));
        rm1 = fmaxf(rm1, __shfl_xor_sync(0xffffffffu, rm1, 2));

        float m0n = fmaxf(m0, rm0), m1n = fmaxf(m1, rm1);
        float a0 = __expf(m0 - m0n), a1 = __expf(m1 - m1n);
        float ps0 = 0.0f, ps1 = 0.0f;
        #pragma unroll
        for (int n = 0; n < 8; n++) {
            Sv[n * 4 + 0] = __expf(Sv[n * 4 + 0] - m0n);
            Sv[n * 4 + 1] = __expf(Sv[n * 4 + 1] - m0n);
            Sv[n * 4 + 2] = __expf(Sv[n * 4 + 2] - m1n);
            Sv[n * 4 + 3] = __expf(Sv[n * 4 + 3] - m1n);
            ps0 += Sv[n * 4 + 0] + Sv[n * 4 + 1];
            ps1 += Sv[n * 4 + 2] + Sv[n * 4 + 3];
        }
        ps0 += __shfl_xor_sync(0xffffffffu, ps0, 1);
        ps0 += __shfl_xor_sync(0xffffffffu, ps0, 2);
        ps1 += __shfl_xor_sync(0xffffffffu, ps1, 1);
        ps1 += __shfl_xor_sync(0xffffffffu, ps1, 2);

        l0 = l0 * a0 + ps0;  m0 = m0n;
        l1 = l1 * a1 + ps1;  m1 = m1n;
        #pragma unroll
        for (int n = 0; n < 8; n++) {
            O[n * 4 + 0] *= a0;  O[n * 4 + 1] *= a0;
            O[n * 4 + 2] *= a1;  O[n * 4 + 3] *= a1;
        }

        // ---- P fragments: C-layout == A-layout, split in registers ----
        uint32_t Ph[4][4], Pl[4][4];
        #pragma unroll
        for (int ks = 0; ks < 4; ks++) {
            bsplit2(Sv[(2*ks)   * 4 + 0], Sv[(2*ks)   * 4 + 1], Ph[ks][0], Pl[ks][0]);
            bsplit2(Sv[(2*ks)   * 4 + 2], Sv[(2*ks)   * 4 + 3], Ph[ks][1], Pl[ks][1]);
            bsplit2(Sv[(2*ks+1) * 4 + 0], Sv[(2*ks+1) * 4 + 1], Ph[ks][2], Pl[ks][2]);
            bsplit2(Sv[(2*ks+1) * 4 + 2], Sv[(2*ks+1) * 4 + 3], Ph[ks][3], Pl[ks][3]);
        }

        // ---- O += P @ V ----
        #pragma unroll
        for (int ks = 0; ks < 4; ks++) {
            #pragma unroll
            for (int n = 0; n < 8; n++) {
                uint32_t base = (uint32_t)(ks * 8 + tg) * 72 + n * 8 + g;
                uint32_t bh0 = sw[SM_VHI + base];
                uint32_t bh1 = sw[SM_VHI + base + 4 * 72];
                uint32_t bl0 = sw[SM_VLO + base];
                uint32_t bl1 = sw[SM_VLO + base + 4 * 72];
                float* d = &O[n * 4];
                mma_bf16(d, Ph[ks], bh0, bh1);
                mma_bf16(d, Ph[ks], bl0, bl1);
                mma_bf16(d, Pl[ks], bh0, bh1);
            }
        }
    }

    // ---- finalize and write O ----
    float inv0 = 1.0f / l0, inv1 = 1.0f / l1;
    float* Og = g_O + ((size_t)b * HW_ + qt * 128 + w * 16) * C_;
    #pragma unroll
    for (int n = 0; n < 8; n++) {
        int col = n * 8 + 2 * tg;
        *(float2*)&Og[g * 64 + col]       = make_float2(O[n*4+0] * inv0, O[n*4+1] * inv0);
        *(float2*)&Og[(g + 8) * 64 + col] = make_float2(O[n*4+2] * inv1, O[n*4+3] * inv1);
    }
}

// ---------------------------------------------------------------------------
// Kernel 3: mixed = relu(O @ wm^T + bm) + exact 2x2 avg pool (unchanged).
// ---------------------------------------------------------------------------
__global__ void mixpool_kernel(const float* __restrict__ wm,
                               const float* __restrict__ bm,
                               float* __restrict__ out)
{
    extern __shared__ float sm[];
    float* Os  = sm;
    float* wms = Os + 128 * PAD;

    const int b  = blockIdx.y;
    const int oy = blockIdx.x;
    const int t  = threadIdx.x;

    const float* Og = g_O + ((size_t)b * HW_ + oy * 2 * 64) * C_;
    for (int idx = t; idx < 128 * 64; idx += 256) {
        int n = idx >> 6, c = idx & 63;
        Os[n * PAD + c] = Og[idx];
    }
    for (int idx = t; idx < 64 * 64; idx += 256) {
        int d = idx >> 6, c = idx & 63;
        wms[d * PAD + c] = wm[idx];
    }
    __syncthreads();

    #pragma unroll
    for (int k = 0; k < 8; k++) {
        int oidx = t + k * 256;
        int ch   = oidx >> 5;
        int ox   = oidx & 31;
        float bias = bm[ch];
        float s = 0.0f;
        #pragma unroll
        for (int dy = 0; dy < 2; dy++) {
            #pragma unroll
            for (int dx = 0; dx < 2; dx++) {
                int tl = dy * 64 + ox * 2 + dx;
                float a = bias;
                for (int c = 0; c < 64; c += 4) {
                    float4 ov = *(const float4*)&Os[tl * PAD + c];
                    float4 wv = *(const float4*)&wms[ch * PAD + c];
                    a += ov.x * wv.x + ov.y * wv.y + ov.z * wv.z + ov.w * wv.w;
                }
                s += fmaxf(a, 0.0f);
            }
        }
        out[(((size_t)b * C_ + ch) * 32 + oy) * 32 + ox] = 0.25f * s;
    }
}

// ---------------------------------------------------------------------------
extern "C" void kernel_launch(void* const* d_in, const int* in_sizes, int n_in,
                              void* d_out, int out_size)
{
    const float* x  = (const float*)d_in[0];
    const float* wq = (const float*)d_in[1];
    const float* bq = (const float*)d_in[2];
    const float* wk = (const float*)d_in[3];
    const float* bk = (const float*)d_in[4];
    const float* wv = (const float*)d_in[5];
    const float* bv = (const float*)d_in[6];
    const float* wm = (const float*)d_in[7];
    const float* bm = (const float*)d_in[8];
    float* out = (float*)d_out;

    const int smem_proj = 4 * 64 * PAD * sizeof(float);            // 69632
    const int smem_attn = SM_WORDS * sizeof(uint32_t);             // 36864
    const int smem_mix  = (128 + 64) * PAD * sizeof(float);        // 52224

    cudaFuncSetAttribute(proj_kernel,    cudaFuncAttributeMaxDynamicSharedMemorySize, smem_proj);
    cudaFuncSetAttribute(attn_kernel,    cudaFuncAttributeMaxDynamicSharedMemorySize, smem_attn);
    cudaFuncSetAttribute(mixpool_kernel, cudaFuncAttributeMaxDynamicSharedMemorySize, smem_mix);

    proj_kernel<<<dim3(64, B_), 256, smem_proj>>>(x, wq, bq, wk, bk, wv, bv);
    attn_kernel<<<dim3(32, B_), 256, smem_attn>>>();
    mixpool_kernel<<<dim3(32, B_), 256, smem_mix>>>(wm, bm, out);
}

// round 6
// speedup vs baseline: 18.3447x; 1.5854x over previous
#include <cuda_runtime.h>
#include <cuda_bf16.h>
#include <math.h>
#include <stdint.h>

// Problem constants
#define B_   8
#define C_   64
#define HW_  4096      // 64*64 tokens

// Scratch (allocation-free rule: __device__ globals)
__device__ float g_Q[B_ * HW_ * C_];
__device__ float g_K[B_ * HW_ * C_];
__device__ float g_V[B_ * HW_ * C_];
__device__ float g_O[B_ * HW_ * C_];

// ---------------------------------------------------------------------------
// Shared helpers: bf16 split (hi + lo covers ~16 mantissa bits -> fp32-grade
// with 3-term mma) and the m16n8k16 bf16 mma wrapper.
// ---------------------------------------------------------------------------
__device__ __forceinline__ void bsplit2(float x, float y, uint32_t& hi, uint32_t& lo)
{
    __nv_bfloat162 h = __floats2bfloat162_rn(x, y);
    float2 hf = __bfloat1622float2(h);
    __nv_bfloat162 l = __floats2bfloat162_rn(x - hf.x, y - hf.y);
    hi = *reinterpret_cast<uint32_t*>(&h);
    lo = *reinterpret_cast<uint32_t*>(&l);
}

__device__ __forceinline__ void mma_bf16(float* d, const uint32_t* a, uint32_t b0, uint32_t b1)
{
    asm volatile(
        "mma.sync.aligned.m16n8k16.row.col.f32.bf16.bf16.f32 "
        "{%0,%1,%2,%3}, {%4,%5,%6,%7}, {%8,%9}, {%0,%1,%2,%3};\n"
        : "+f"(d[0]), "+f"(d[1]), "+f"(d[2]), "+f"(d[3])
        : "r"(a[0]), "r"(a[1]), "r"(a[2]), "r"(a[3]), "r"(b0), "r"(b1));
}

// ---------------------------------------------------------------------------
// Kernel 1: Q/K/V projections via tensor cores.
// q[b,n,d] = sum_c x[b,c,n] * wq[d,c] + bq[d]  (x transposed while staging).
// Grid: (32 tiles of 128 tokens, 8 batches), 256 threads = 8 warps.
// smem words: xhi[128][36], xlo, then per-matrix whi[64][36], wlo.
// ---------------------------------------------------------------------------
#define PJ_XHI 0
#define PJ_XLO 4608
#define PJ_W0  9216
#define PJ_WORDS (9216 + 3 * 4608)   // 23040 words = 92160 B

__global__ __launch_bounds__(256, 2) void proj_kernel(
    const float* __restrict__ x,
    const float* __restrict__ wq, const float* __restrict__ bq,
    const float* __restrict__ wk, const float* __restrict__ bk,
    const float* __restrict__ wv, const float* __restrict__ bv)
{
    extern __shared__ uint32_t sw[];

    const int b    = blockIdx.y;
    const int n0   = blockIdx.x * 128;
    const int t    = threadIdx.x;
    const int w    = t >> 5;
    const int lane = t & 31;
    const int g    = lane >> 2;
    const int tg   = lane & 3;

    const float* xb = x + (size_t)b * C_ * HW_;

    // ---- stage x tile: transpose [c][n] -> bf16x2 hi/lo [n][cp] ----
    #pragma unroll
    for (int i = 0; i < 16; i++) {
        int idx = t + i * 256;            // 0..4095
        int cp = idx >> 7, n = idx & 127; // coalesced over n
        float v0 = xb[(2 * cp)     * HW_ + n0 + n];
        float v1 = xb[(2 * cp + 1) * HW_ + n0 + n];
        uint32_t h, l;
        bsplit2(v0, v1, h, l);
        sw[PJ_XHI + n * 36 + cp] = h;
        sw[PJ_XLO + n * 36 + cp] = l;
    }
    // ---- stage all three weight matrices in B-layout hi/lo ----
    {
        const float* wp[3] = { wq, wk, wv };
        #pragma unroll
        for (int m = 0; m < 3; m++) {
            const float* W = wp[m];
            uint32_t base = PJ_W0 + m * 4608;
            #pragma unroll
            for (int i = 0; i < 8; i++) {
                int idx = t + i * 256;        // 0..2047
                int d = idx >> 5, cp = idx & 31;
                float2 wv2 = *(const float2*)&W[d * 64 + 2 * cp];
                uint32_t h, l;
                bsplit2(wv2.x, wv2.y, h, l);
                sw[base + d * 36 + cp]        = h;
                sw[base + 2304 + d * 36 + cp] = l;
            }
        }
    }
    __syncthreads();

    // ---- A fragments for this warp's 16 tokens (4 k-steps, hi/lo) ----
    uint32_t Ahi[4][4], Alo[4][4];
    #pragma unroll
    for (int ks = 0; ks < 4; ks++) {
        uint32_t r0 = (uint32_t)(w * 16 + g) * 36 + ks * 8 + tg;
        uint32_t r1 = r0 + 8 * 36;
        Ahi[ks][0] = sw[PJ_XHI + r0];     Alo[ks][0] = sw[PJ_XLO + r0];
        Ahi[ks][1] = sw[PJ_XHI + r1];     Alo[ks][1] = sw[PJ_XLO + r1];
        Ahi[ks][2] = sw[PJ_XHI + r0 + 4]; Alo[ks][2] = sw[PJ_XLO + r0 + 4];
        Ahi[ks][3] = sw[PJ_XHI + r1 + 4]; Alo[ks][3] = sw[PJ_XLO + r1 + 4];
    }

    const float* bp[3] = { bq, bk, bv };
    float* op[3] = { g_Q, g_K, g_V };

    #pragma unroll
    for (int m = 0; m < 3; m++) {
        const uint32_t whi = PJ_W0 + m * 4608;
        const uint32_t wlo = whi + 2304;
        float acc[32];
        #pragma unroll
        for (int n = 0; n < 8; n++) {
            float b0 = bp[m][n * 8 + 2 * tg];
            float b1 = bp[m][n * 8 + 2 * tg + 1];
            acc[n * 4 + 0] = b0; acc[n * 4 + 1] = b1;
            acc[n * 4 + 2] = b0; acc[n * 4 + 3] = b1;
        }
        #pragma unroll
        for (int ks = 0; ks < 4; ks++) {
            #pragma unroll
            for (int n = 0; n < 8; n++) {
                uint32_t base = (uint32_t)(n * 8 + g) * 36 + tg + ks * 8;
                uint32_t bh0 = sw[whi + base];
                uint32_t bh1 = sw[whi + base + 4];
                uint32_t bl0 = sw[wlo + base];
                uint32_t bl1 = sw[wlo + base + 4];
                float* d = &acc[n * 4];
                mma_bf16(d, Ahi[ks], bh0, bh1);
                mma_bf16(d, Ahi[ks], bl0, bl1);
                mma_bf16(d, Alo[ks], bh0, bh1);
            }
        }
        float* og = op[m] + ((size_t)b * HW_ + n0 + w * 16) * C_;
        #pragma unroll
        for (int n = 0; n < 8; n++) {
            int col = n * 8 + 2 * tg;
            *(float2*)&og[g * 64 + col]       = make_float2(acc[n*4+0], acc[n*4+1]);
            *(float2*)&og[(g + 8) * 64 + col] = make_float2(acc[n*4+2], acc[n*4+3]);
        }
    }
}

// ---------------------------------------------------------------------------
// Kernel 2: tensor-core flash attention (unchanged from R4 — known good).
// ---------------------------------------------------------------------------
#define SM_KHI 0
#define SM_KLO 2304
#define SM_VHI 4608
#define SM_VLO 6912
#define SM_WORDS 9216

__global__ __launch_bounds__(256, 2) void attn_kernel()
{
    extern __shared__ uint32_t sw[];

    const int b    = blockIdx.y;
    const int qt   = blockIdx.x;
    const int t    = threadIdx.x;
    const int w    = t >> 5;
    const int lane = t & 31;
    const int g    = lane >> 2;
    const int tg   = lane & 3;

    uint32_t Ahi[4][4], Alo[4][4];
    {
        const float* Qg = g_Q + ((size_t)b * HW_ + qt * 128 + w * 16) * C_;
        #pragma unroll
        for (int ks = 0; ks < 4; ks++) {
            int cb = ks * 16 + 2 * tg;
            float2 q00 = *(const float2*)&Qg[g * 64 + cb];
            float2 q10 = *(const float2*)&Qg[(g + 8) * 64 + cb];
            float2 q01 = *(const float2*)&Qg[g * 64 + cb + 8];
            float2 q11 = *(const float2*)&Qg[(g + 8) * 64 + cb + 8];
            bsplit2(q00.x * 0.125f, q00.y * 0.125f, Ahi[ks][0], Alo[ks][0]);
            bsplit2(q10.x * 0.125f, q10.y * 0.125f, Ahi[ks][1], Alo[ks][1]);
            bsplit2(q01.x * 0.125f, q01.y * 0.125f, Ahi[ks][2], Alo[ks][2]);
            bsplit2(q11.x * 0.125f, q11.y * 0.125f, Ahi[ks][3], Alo[ks][3]);
        }
    }

    float O[32];
    #pragma unroll
    for (int j = 0; j < 32; j++) O[j] = 0.0f;
    float m0 = -1e30f, m1 = -1e30f, l0 = 0.0f, l1 = 0.0f;

    const float* Kb = g_K + (size_t)b * HW_ * C_;
    const float* Vb = g_V + (size_t)b * HW_ * C_;

    for (int kt = 0; kt < 64; kt++) {
        __syncthreads();
        const float* Kg = Kb + kt * 64 * C_;
        const float* Vg = Vb + kt * 64 * C_;

        #pragma unroll
        for (int i = 0; i < 8; i++) {
            int idx = t + i * 256;
            int key = idx >> 5, cp = idx & 31;
            float2 kv = *(const float2*)&Kg[key * 64 + 2 * cp];
            uint32_t h, l;
            bsplit2(kv.x, kv.y, h, l);
            sw[SM_KHI + key * 36 + cp] = h;
            sw[SM_KLO + key * 36 + cp] = l;
        }
        #pragma unroll
        for (int i = 0; i < 8; i++) {
            int idx = t + i * 256;
            int ch = idx & 63, kp = idx >> 6;
            float v0 = Vg[(2 * kp) * 64 + ch];
            float v1 = Vg[(2 * kp + 1) * 64 + ch];
            uint32_t h, l;
            bsplit2(v0, v1, h, l);
            sw[SM_VHI + kp * 72 + ch] = h;
            sw[SM_VLO + kp * 72 + ch] = l;
        }
        __syncthreads();

        float Sv[32];
        #pragma unroll
        for (int j = 0; j < 32; j++) Sv[j] = 0.0f;

        #pragma unroll
        for (int ks = 0; ks < 4; ks++) {
            #pragma unroll
            for (int n = 0; n < 8; n++) {
                uint32_t base = (uint32_t)(n * 8 + g) * 36 + tg + ks * 8;
                uint32_t bh0 = sw[SM_KHI + base];
                uint32_t bh1 = sw[SM_KHI + base + 4];
                uint32_t bl0 = sw[SM_KLO + base];
                uint32_t bl1 = sw[SM_KLO + base + 4];
                float* d = &Sv[n * 4];
                mma_bf16(d, Ahi[ks], bh0, bh1);
                mma_bf16(d, Ahi[ks], bl0, bl1);
                mma_bf16(d, Alo[ks], bh0, bh1);
            }
        }

        float rm0 = -1e30f, rm1 = -1e30f;
        #pragma unroll
        for (int n = 0; n < 8; n++) {
            rm0 = fmaxf(rm0, fmaxf(Sv[n * 4 + 0], Sv[n * 4 + 1]));
            rm1 = fmaxf(rm1, fmaxf(Sv[n * 4 + 2], Sv[n * 4 + 3]));
        }
        rm0 = fmaxf(rm0, __shfl_xor_sync(0xffffffffu, rm0, 1));
        rm0 = fmaxf(rm0, __shfl_xor_sync(0xffffffffu, rm0, 2));
        rm1 = fmaxf(rm1, __shfl_xor_sync(0xffffffffu, rm1, 1));
        rm1 = fmaxf(rm1, __shfl_xor_sync(0xffffffffu, rm1, 2));

        float m0n = fmaxf(m0, rm0), m1n = fmaxf(m1, rm1);
        float a0 = __expf(m0 - m0n), a1 = __expf(m1 - m1n);
        float ps0 = 0.0f, ps1 = 0.0f;
        #pragma unroll
        for (int n = 0; n < 8; n++) {
            Sv[n * 4 + 0] = __expf(Sv[n * 4 + 0] - m0n);
            Sv[n * 4 + 1] = __expf(Sv[n * 4 + 1] - m0n);
            Sv[n * 4 + 2] = __expf(Sv[n * 4 + 2] - m1n);
            Sv[n * 4 + 3] = __expf(Sv[n * 4 + 3] - m1n);
            ps0 += Sv[n * 4 + 0] + Sv[n * 4 + 1];
            ps1 += Sv[n * 4 + 2] + Sv[n * 4 + 3];
        }
        ps0 += __shfl_xor_sync(0xffffffffu, ps0, 1);
        ps0 += __shfl_xor_sync(0xffffffffu, ps0, 2);
        ps1 += __shfl_xor_sync(0xffffffffu, ps1, 1);
        ps1 += __shfl_xor_sync(0xffffffffu, ps1, 2);

        l0 = l0 * a0 + ps0;  m0 = m0n;
        l1 = l1 * a1 + ps1;  m1 = m1n;
        #pragma unroll
        for (int n = 0; n < 8; n++) {
            O[n * 4 + 0] *= a0;  O[n * 4 + 1] *= a0;
            O[n * 4 + 2] *= a1;  O[n * 4 + 3] *= a1;
        }

        uint32_t Ph[4][4], Pl[4][4];
        #pragma unroll
        for (int ks = 0; ks < 4; ks++) {
            bsplit2(Sv[(2*ks)   * 4 + 0], Sv[(2*ks)   * 4 + 1], Ph[ks][0], Pl[ks][0]);
            bsplit2(Sv[(2*ks)   * 4 + 2], Sv[(2*ks)   * 4 + 3], Ph[ks][1], Pl[ks][1]);
            bsplit2(Sv[(2*ks+1) * 4 + 0], Sv[(2*ks+1) * 4 + 1], Ph[ks][2], Pl[ks][2]);
            bsplit2(Sv[(2*ks+1) * 4 + 2], Sv[(2*ks+1) * 4 + 3], Ph[ks][3], Pl[ks][3]);
        }

        #pragma unroll
        for (int ks = 0; ks < 4; ks++) {
            #pragma unroll
            for (int n = 0; n < 8; n++) {
                uint32_t base = (uint32_t)(ks * 8 + tg) * 72 + n * 8 + g;
                uint32_t bh0 = sw[SM_VHI + base];
                uint32_t bh1 = sw[SM_VHI + base + 4 * 72];
                uint32_t bl0 = sw[SM_VLO + base];
                uint32_t bl1 = sw[SM_VLO + base + 4 * 72];
                float* d = &O[n * 4];
                mma_bf16(d, Ph[ks], bh0, bh1);
                mma_bf16(d, Ph[ks], bl0, bl1);
                mma_bf16(d, Pl[ks], bh0, bh1);
            }
        }
    }

    float inv0 = 1.0f / l0, inv1 = 1.0f / l1;
    float* Og = g_O + ((size_t)b * HW_ + qt * 128 + w * 16) * C_;
    #pragma unroll
    for (int n = 0; n < 8; n++) {
        int col = n * 8 + 2 * tg;
        *(float2*)&Og[g * 64 + col]       = make_float2(O[n*4+0] * inv0, O[n*4+1] * inv0);
        *(float2*)&Og[(g + 8) * 64 + col] = make_float2(O[n*4+2] * inv1, O[n*4+3] * inv1);
    }
}

// ---------------------------------------------------------------------------
// Kernel 3: mixed = relu(O @ wm^T + bm) via tensor cores, then exact 2x2
// average pool (bilinear 64->32 half-pixel == avg pool). Tile = 128 tokens
// = image rows 2oy, 2oy+1. A-frags loaded straight from g_O.
// smem: wmhi[64][36], wmlo, then mixed float[128][68].
// ---------------------------------------------------------------------------
#define MX_WHI 0
#define MX_WLO 2304
#define MX_MS  4608                       // float region starts here (words)
#define MX_WORDS (4608 + 128 * 68)        // 13312 words = 53248 B

__global__ __launch_bounds__(256, 2) void mixpool_kernel(
    const float* __restrict__ wm,
    const float* __restrict__ bm,
    float* __restrict__ out)
{
    extern __shared__ uint32_t sw[];
    float* ms = (float*)&sw[MX_MS];

    const int b    = blockIdx.y;
    const int oy   = blockIdx.x;
    const int t    = threadIdx.x;
    const int w    = t >> 5;
    const int lane = t & 31;
    const int g    = lane >> 2;
    const int tg   = lane & 3;

    // stage wm in B-layout hi/lo
    #pragma unroll
    for (int i = 0; i < 8; i++) {
        int idx = t + i * 256;
        int d = idx >> 5, cp = idx & 31;
        float2 wv2 = *(const float2*)&wm[d * 64 + 2 * cp];
        uint32_t h, l;
        bsplit2(wv2.x, wv2.y, h, l);
        sw[MX_WHI + d * 36 + cp] = h;
        sw[MX_WLO + d * 36 + cp] = l;
    }

    // A fragments straight from g_O (this warp's 16 tokens)
    uint32_t Ahi[4][4], Alo[4][4];
    {
        const float* Og = g_O + ((size_t)b * HW_ + oy * 128 + w * 16) * C_;
        #pragma unroll
        for (int ks = 0; ks < 4; ks++) {
            int cb = ks * 16 + 2 * tg;
            float2 q00 = *(const float2*)&Og[g * 64 + cb];
            float2 q10 = *(const float2*)&Og[(g + 8) * 64 + cb];
            float2 q01 = *(const float2*)&Og[g * 64 + cb + 8];
            float2 q11 = *(const float2*)&Og[(g + 8) * 64 + cb + 8];
            bsplit2(q00.x, q00.y, Ahi[ks][0], Alo[ks][0]);
            bsplit2(q10.x, q10.y, Ahi[ks][1], Alo[ks][1]);
            bsplit2(q01.x, q01.y, Ahi[ks][2], Alo[ks][2]);
            bsplit2(q11.x, q11.y, Ahi[ks][3], Alo[ks][3]);
        }
    }
    __syncthreads();

    float acc[32];
    #pragma unroll
    for (int n = 0; n < 8; n++) {
        float b0 = bm[n * 8 + 2 * tg];
        float b1 = bm[n * 8 + 2 * tg + 1];
        acc[n * 4 + 0] = b0; acc[n * 4 + 1] = b1;
        acc[n * 4 + 2] = b0; acc[n * 4 + 3] = b1;
    }
    #pragma unroll
    for (int ks = 0; ks < 4; ks++) {
        #pragma unroll
        for (int n = 0; n < 8; n++) {
            uint32_t base = (uint32_t)(n * 8 + g) * 36 + tg + ks * 8;
            uint32_t bh0 = sw[MX_WHI + base];
            uint32_t bh1 = sw[MX_WHI + base + 4];
            uint32_t bl0 = sw[MX_WLO + base];
            uint32_t bl1 = sw[MX_WLO + base + 4];
            float* d = &acc[n * 4];
            mma_bf16(d, Ahi[ks], bh0, bh1);
            mma_bf16(d, Ahi[ks], bl0, bl1);
            mma_bf16(d, Alo[ks], bh0, bh1);
        }
    }

    // relu + store mixed to smem [token][ch]
    {
        int r0 = w * 16 + g, r1 = r0 + 8;
        #pragma unroll
        for (int n = 0; n < 8; n++) {
            int col = n * 8 + 2 * tg;
            *(float2*)&ms[r0 * 68 + col] =
                make_float2(fmaxf(acc[n*4+0], 0.0f), fmaxf(acc[n*4+1], 0.0f));
            *(float2*)&ms[r1 * 68 + col] =
                make_float2(fmaxf(acc[n*4+2], 0.0f), fmaxf(acc[n*4+3], 0.0f));
        }
    }
    __syncthreads();

    // 2x2 average pool: tokens {2ox, 2ox+1} of rows 2oy (0..63) and 2oy+1 (64..127)
    #pragma unroll
    for (int k = 0; k < 8; k++) {
        int oidx = t + k * 256;           // (ch, ox)
        int ch = oidx >> 5, ox = oidx & 31;
        float s = ms[(2 * ox)      * 68 + ch]
                + ms[(2 * ox + 1)  * 68 + ch]
                + ms[(64 + 2 * ox) * 68 + ch]
                + ms[(65 + 2 * ox) * 68 + ch];
        out[(((size_t)b * C_ + ch) * 32 + oy) * 32 + ox] = 0.25f * s;
    }
}

// ---------------------------------------------------------------------------
extern "C" void kernel_launch(void* const* d_in, const int* in_sizes, int n_in,
                              void* d_out, int out_size)
{
    const float* x  = (const float*)d_in[0];
    const float* wq = (const float*)d_in[1];
    const float* bq = (const float*)d_in[2];
    const float* wk = (const float*)d_in[3];
    const float* bk = (const float*)d_in[4];
    const float* wv = (const float*)d_in[5];
    const float* bv = (const float*)d_in[6];
    const float* wm = (const float*)d_in[7];
    const float* bm = (const float*)d_in[8];
    float* out = (float*)d_out;

    const int smem_proj = PJ_WORDS * sizeof(uint32_t);   // 92160
    const int smem_attn = SM_WORDS * sizeof(uint32_t);   // 36864
    const int smem_mix  = MX_WORDS * sizeof(uint32_t);   // 53248

    cudaFuncSetAttribute(proj_kernel,    cudaFuncAttributeMaxDynamicSharedMemorySize, smem_proj);
    cudaFuncSetAttribute(attn_kernel,    cudaFuncAttributeMaxDynamicSharedMemorySize, smem_attn);
    cudaFuncSetAttribute(mixpool_kernel, cudaFuncAttributeMaxDynamicSharedMemorySize, smem_mix);

    proj_kernel<<<dim3(32, B_), 256, smem_proj>>>(x, wq, bq, wk, bk, wv, bv);
    attn_kernel<<<dim3(32, B_), 256, smem_attn>>>();
    mixpool_kernel<<<dim3(32, B_), 256, smem_mix>>>(wm, bm, out);
}

// round 7
// speedup vs baseline: 21.1055x; 1.1505x over previous
#include <cuda_runtime.h>
#include <cuda_bf16.h>
#include <math.h>
#include <stdint.h>

// Problem constants
#define B_   8
#define C_   64
#define HW_  4096      // 64*64 tokens

// Scratch (allocation-free rule: __device__ globals)
__device__ float    g_V [B_ * HW_ * C_];            // fp32 V (for vconv)
__device__ float    g_O [B_ * HW_ * C_];            // attention output fp32
__device__ uint32_t g_Qhi[B_ * HW_ * 32];           // Q bf16x2 hi (pre-scaled 0.125)
__device__ uint32_t g_Qlo[B_ * HW_ * 32];
__device__ uint32_t g_Khi[B_ * HW_ * 32];           // K bf16x2 hi [token][cp]
__device__ uint32_t g_Klo[B_ * HW_ * 32];
__device__ uint32_t g_Vthi[B_ * 64 * 2048];         // V^T bf16x2 [ch][keypair]
__device__ uint32_t g_Vtlo[B_ * 64 * 2048];

// ---------------------------------------------------------------------------
// Helpers
// ---------------------------------------------------------------------------
__device__ __forceinline__ void bsplit2(float x, float y, uint32_t& hi, uint32_t& lo)
{
    __nv_bfloat162 h = __floats2bfloat162_rn(x, y);
    float2 hf = __bfloat1622float2(h);
    __nv_bfloat162 l = __floats2bfloat162_rn(x - hf.x, y - hf.y);
    hi = *reinterpret_cast<uint32_t*>(&h);
    lo = *reinterpret_cast<uint32_t*>(&l);
}

__device__ __forceinline__ void mma_bf16(float* d, const uint32_t* a, uint32_t b0, uint32_t b1)
{
    asm volatile(
        "mma.sync.aligned.m16n8k16.row.col.f32.bf16.bf16.f32 "
        "{%0,%1,%2,%3}, {%4,%5,%6,%7}, {%8,%9}, {%0,%1,%2,%3};\n"
        : "+f"(d[0]), "+f"(d[1]), "+f"(d[2]), "+f"(d[3])
        : "r"(a[0]), "r"(a[1]), "r"(a[2]), "r"(a[3]), "r"(b0), "r"(b1));
}

__device__ __forceinline__ void ldsm4(uint32_t addr, uint32_t& r0, uint32_t& r1,
                                      uint32_t& r2, uint32_t& r3)
{
    asm volatile("ldmatrix.sync.aligned.m8n8.x4.shared.b16 {%0,%1,%2,%3}, [%4];"
                 : "=r"(r0), "=r"(r1), "=r"(r2), "=r"(r3) : "r"(addr));
}

// ---------------------------------------------------------------------------
// Kernel 1: Q/K/V projections via tensor cores (R5 core).
// Writes Q,K as split-bf16 packed words, V as fp32.
// ---------------------------------------------------------------------------
#define PJ_XHI 0
#define PJ_XLO 4608
#define PJ_W0  9216
#define PJ_WORDS (9216 + 3 * 4608)   // 23040 words = 92160 B

__global__ __launch_bounds__(256, 2) void proj_kernel(
    const float* __restrict__ x,
    const float* __restrict__ wq, const float* __restrict__ bq,
    const float* __restrict__ wk, const float* __restrict__ bk,
    const float* __restrict__ wv, const float* __restrict__ bv)
{
    extern __shared__ uint32_t sw[];

    const int b    = blockIdx.y;
    const int n0   = blockIdx.x * 128;
    const int t    = threadIdx.x;
    const int w    = t >> 5;
    const int lane = t & 31;
    const int g    = lane >> 2;
    const int tg   = lane & 3;

    const float* xb = x + (size_t)b * C_ * HW_;

    #pragma unroll
    for (int i = 0; i < 16; i++) {
        int idx = t + i * 256;
        int cp = idx >> 7, n = idx & 127;
        float v0 = xb[(2 * cp)     * HW_ + n0 + n];
        float v1 = xb[(2 * cp + 1) * HW_ + n0 + n];
        uint32_t h, l;
        bsplit2(v0, v1, h, l);
        sw[PJ_XHI + n * 36 + cp] = h;
        sw[PJ_XLO + n * 36 + cp] = l;
    }
    {
        const float* wp[3] = { wq, wk, wv };
        #pragma unroll
        for (int m = 0; m < 3; m++) {
            const float* W = wp[m];
            uint32_t base = PJ_W0 + m * 4608;
            #pragma unroll
            for (int i = 0; i < 8; i++) {
                int idx = t + i * 256;
                int d = idx >> 5, cp = idx & 31;
                float2 wv2 = *(const float2*)&W[d * 64 + 2 * cp];
                uint32_t h, l;
                bsplit2(wv2.x, wv2.y, h, l);
                sw[base + d * 36 + cp]        = h;
                sw[base + 2304 + d * 36 + cp] = l;
            }
        }
    }
    __syncthreads();

    uint32_t Ahi[4][4], Alo[4][4];
    #pragma unroll
    for (int ks = 0; ks < 4; ks++) {
        uint32_t r0 = (uint32_t)(w * 16 + g) * 36 + ks * 8 + tg;
        uint32_t r1 = r0 + 8 * 36;
        Ahi[ks][0] = sw[PJ_XHI + r0];     Alo[ks][0] = sw[PJ_XLO + r0];
        Ahi[ks][1] = sw[PJ_XHI + r1];     Alo[ks][1] = sw[PJ_XLO + r1];
        Ahi[ks][2] = sw[PJ_XHI + r0 + 4]; Alo[ks][2] = sw[PJ_XLO + r0 + 4];
        Ahi[ks][3] = sw[PJ_XHI + r1 + 4]; Alo[ks][3] = sw[PJ_XLO + r1 + 4];
    }

    const float* bp[3] = { bq, bk, bv };
    const size_t tok0 = (size_t)b * HW_ + n0 + w * 16 + g;   // first row token
    const size_t tok1 = tok0 + 8;

    #pragma unroll
    for (int m = 0; m < 3; m++) {
        const uint32_t whi = PJ_W0 + m * 4608;
        const uint32_t wlo = whi + 2304;
        float acc[32];
        #pragma unroll
        for (int n = 0; n < 8; n++) {
            float b0 = bp[m][n * 8 + 2 * tg];
            float b1 = bp[m][n * 8 + 2 * tg + 1];
            acc[n * 4 + 0] = b0; acc[n * 4 + 1] = b1;
            acc[n * 4 + 2] = b0; acc[n * 4 + 3] = b1;
        }
        #pragma unroll
        for (int ks = 0; ks < 4; ks++) {
            #pragma unroll
            for (int n = 0; n < 8; n++) {
                uint32_t base = (uint32_t)(n * 8 + g) * 36 + tg + ks * 8;
                uint32_t bh0 = sw[whi + base];
                uint32_t bh1 = sw[whi + base + 4];
                uint32_t bl0 = sw[wlo + base];
                uint32_t bl1 = sw[wlo + base + 4];
                float* d = &acc[n * 4];
                mma_bf16(d, Ahi[ks], bh0, bh1);
                mma_bf16(d, Ahi[ks], bl0, bl1);
                mma_bf16(d, Alo[ks], bh0, bh1);
            }
        }
        if (m == 0) {
            // Q: fold softmax scale, write split
            #pragma unroll
            for (int n = 0; n < 8; n++) {
                uint32_t h, l;
                bsplit2(acc[n*4+0] * 0.125f, acc[n*4+1] * 0.125f, h, l);
                g_Qhi[tok0 * 32 + n * 4 + tg] = h;
                g_Qlo[tok0 * 32 + n * 4 + tg] = l;
                bsplit2(acc[n*4+2] * 0.125f, acc[n*4+3] * 0.125f, h, l);
                g_Qhi[tok1 * 32 + n * 4 + tg] = h;
                g_Qlo[tok1 * 32 + n * 4 + tg] = l;
            }
        } else if (m == 1) {
            // K: write split
            #pragma unroll
            for (int n = 0; n < 8; n++) {
                uint32_t h, l;
                bsplit2(acc[n*4+0], acc[n*4+1], h, l);
                g_Khi[tok0 * 32 + n * 4 + tg] = h;
                g_Klo[tok0 * 32 + n * 4 + tg] = l;
                bsplit2(acc[n*4+2], acc[n*4+3], h, l);
                g_Khi[tok1 * 32 + n * 4 + tg] = h;
                g_Klo[tok1 * 32 + n * 4 + tg] = l;
            }
        } else {
            // V: fp32 (vconv transposes+splits)
            float* og = g_V + tok0 * C_;   // note: row base, cols via n
            #pragma unroll
            for (int n = 0; n < 8; n++) {
                int col = n * 8 + 2 * tg;
                *(float2*)&og[col]            = make_float2(acc[n*4+0], acc[n*4+1]);
                *(float2*)&og[8 * C_ + col]   = make_float2(acc[n*4+2], acc[n*4+3]);
            }
        }
    }
}

// ---------------------------------------------------------------------------
// Kernel 1b: V -> transposed split bf16  vt[ch][keypair]
// Grid (64 chunks of 64 keys, 8 batches), 256 threads.
// ---------------------------------------------------------------------------
__global__ __launch_bounds__(256) void vconv_kernel()
{
    __shared__ float vs[64 * 65];
    const int b  = blockIdx.y;
    const int kt = blockIdx.x;
    const int t  = threadIdx.x;

    const float* Vg = g_V + ((size_t)b * HW_ + kt * 64) * C_;
    #pragma unroll
    for (int i = 0; i < 16; i++) {
        int idx = t + i * 256;
        int key = idx >> 6, ch = idx & 63;
        vs[key * 65 + ch] = Vg[idx];
    }
    __syncthreads();
    #pragma unroll
    for (int i = 0; i < 8; i++) {
        int idx = t + i * 256;
        int kp = idx & 31, ch = idx >> 5;
        float v0 = vs[(2 * kp)     * 65 + ch];
        float v1 = vs[(2 * kp + 1) * 65 + ch];
        uint32_t h, l;
        bsplit2(v0, v1, h, l);
        size_t o = ((size_t)b * 64 + ch) * 2048 + kt * 32 + kp;
        g_Vthi[o] = h;
        g_Vtlo[o] = l;
    }
}

// ---------------------------------------------------------------------------
// Kernel 2: flash attention — cp.async double-buffered, ldmatrix B-frags.
// smem per buffer (words): KHI[64][36], KLO, VHI[64ch][36], VLO  = 9216
// ---------------------------------------------------------------------------
#define AB_KHI 0
#define AB_KLO 2304
#define AB_VHI 4608
#define AB_VLO 6912
#define AB_BUF 9216
#define AB_WORDS (2 * AB_BUF)        // 18432 words = 73728 B

__device__ __forceinline__ void attn_issue(uint32_t sbytes, int bufw, int t,
    const uint32_t* p0, const uint32_t* p1, const uint32_t* p2, const uint32_t* p3)
{
    // 2048 granules of 16B: sec = i/2 (0:Khi 1:Klo 2:Vthi 3:Vtlo)
    #pragma unroll
    for (int i = 0; i < 8; i++) {
        const int sec = i >> 1;
        int gid = i * 256 + t;
        int r  = (gid >> 3) & 63;
        int gr = gid & 7;
        uint32_t saddr = sbytes + (uint32_t)(bufw + sec * 2304 + r * 36 + gr * 4) * 4;
        const uint32_t* src;
        if      (sec == 0) src = p0 + (size_t)r * 32   + gr * 4;
        else if (sec == 1) src = p1 + (size_t)r * 32   + gr * 4;
        else if (sec == 2) src = p2 + (size_t)r * 2048 + gr * 4;
        else               src = p3 + (size_t)r * 2048 + gr * 4;
        asm volatile("cp.async.ca.shared.global [%0], [%1], 16;\n"
                     :: "r"(saddr), "l"(src));
    }
    asm volatile("cp.async.commit_group;\n" ::: "memory");
}

__global__ __launch_bounds__(256, 2) void attn_kernel()
{
    extern __shared__ uint32_t sw[];
    const uint32_t sbytes = (uint32_t)__cvta_generic_to_shared(sw);

    const int b    = blockIdx.y;
    const int qt   = blockIdx.x;
    const int t    = threadIdx.x;
    const int w    = t >> 5;
    const int lane = t & 31;
    const int g    = lane >> 2;
    const int tg   = lane & 3;

    // ---- A fragments: direct loads of pre-split Q ----
    uint32_t Ahi[4][4], Alo[4][4];
    {
        const size_t r0 = ((size_t)b * HW_ + qt * 128 + w * 16 + g) * 32;
        const size_t r1 = r0 + 8 * 32;
        #pragma unroll
        for (int ks = 0; ks < 4; ks++) {
            int cw = ks * 8 + tg;
            Ahi[ks][0] = g_Qhi[r0 + cw];     Alo[ks][0] = g_Qlo[r0 + cw];
            Ahi[ks][1] = g_Qhi[r1 + cw];     Alo[ks][1] = g_Qlo[r1 + cw];
            Ahi[ks][2] = g_Qhi[r0 + cw + 4]; Alo[ks][2] = g_Qlo[r0 + cw + 4];
            Ahi[ks][3] = g_Qhi[r1 + cw + 4]; Alo[ks][3] = g_Qlo[r1 + cw + 4];
        }
    }

    float O[32];
    #pragma unroll
    for (int j = 0; j < 32; j++) O[j] = 0.0f;
    float m0 = -1e30f, m1 = -1e30f, l0 = 0.0f, l1 = 0.0f;

    const uint32_t* Kh = g_Khi + (size_t)b * HW_ * 32;
    const uint32_t* Kl = g_Klo + (size_t)b * HW_ * 32;
    const uint32_t* Vh = g_Vthi + (size_t)b * 64 * 2048;
    const uint32_t* Vl = g_Vtlo + (size_t)b * 64 * 2048;

    // prologue: prefetch chunks 0, 1
    attn_issue(sbytes, 0,      t, Kh,            Kl,            Vh,      Vl);
    attn_issue(sbytes, AB_BUF, t, Kh + 64 * 32,  Kl + 64 * 32,  Vh + 32, Vl + 32);

    for (int kt = 0; kt < 64; kt++) {
        if (kt < 63) asm volatile("cp.async.wait_group 1;\n" ::: "memory");
        else         asm volatile("cp.async.wait_group 0;\n" ::: "memory");
        __syncthreads();

        const int bufw = (kt & 1) * AB_BUF;
        const uint32_t kbase = sbytes + (uint32_t)(bufw + AB_KHI) * 4;
        const uint32_t vbase = sbytes + (uint32_t)(bufw + AB_VHI) * 4;

        // ---- S = Q @ K^T ----
        float Sv[32];
        #pragma unroll
        for (int j = 0; j < 32; j++) Sv[j] = 0.0f;

        #pragma unroll
        for (int ks = 0; ks < 4; ks++) {
            #pragma unroll
            for (int np = 0; np < 4; np++) {
                int ntile = np * 2 + (lane >> 4);
                int row   = ntile * 8 + (lane & 7);
                int colw  = ks * 8 + ((lane >> 3) & 1) * 4;
                uint32_t off = (uint32_t)(row * 36 + colw) * 4;
                uint32_t kh0, kh1, kh2, kh3, kl0, kl1, kl2, kl3;
                ldsm4(kbase + off,             kh0, kh1, kh2, kh3);
                ldsm4(kbase + off + 2304 * 4,  kl0, kl1, kl2, kl3);
                float* d0 = &Sv[(np * 2) * 4];
                float* d1 = &Sv[(np * 2 + 1) * 4];
                mma_bf16(d0, Ahi[ks], kh0, kh1);
                mma_bf16(d0, Ahi[ks], kl0, kl1);
                mma_bf16(d0, Alo[ks], kh0, kh1);
                mma_bf16(d1, Ahi[ks], kh2, kh3);
                mma_bf16(d1, Ahi[ks], kl2, kl3);
                mma_bf16(d1, Alo[ks], kh2, kh3);
            }
        }

        // ---- online softmax ----
        float rm0 = -1e30f, rm1 = -1e30f;
        #pragma unroll
        for (int n = 0; n < 8; n++) {
            rm0 = fmaxf(rm0, fmaxf(Sv[n * 4 + 0], Sv[n * 4 + 1]));
            rm1 = fmaxf(rm1, fmaxf(Sv[n * 4 + 2], Sv[n * 4 + 3]));
        }
        rm0 = fmaxf(rm0, __shfl_xor_sync(0xffffffffu, rm0, 1));
        rm0 = fmaxf(rm0, __shfl_xor_sync(0xffffffffu, rm0, 2));
        rm1 = fmaxf(rm1, __shfl_xor_sync(0xffffffffu, rm1, 1));
        rm1 = fmaxf(rm1, __shfl_xor_sync(0xffffffffu, rm1, 2));

        float m0n = fmaxf(m0, rm0), m1n = fmaxf(m1, rm1);
        float a0 = __expf(m0 - m0n), a1 = __expf(m1 - m1n);
        float ps0 = 0.0f, ps1 = 0.0f;
        #pragma unroll
        for (int n = 0; n < 8; n++) {
            Sv[n * 4 + 0] = __expf(Sv[n * 4 + 0] - m0n);
            Sv[n * 4 + 1] = __expf(Sv[n * 4 + 1] - m0n);
            Sv[n * 4 + 2] = __expf(Sv[n * 4 + 2] - m1n);
            Sv[n * 4 + 3] = __expf(Sv[n * 4 + 3] - m1n);
            ps0 += Sv[n * 4 + 0] + Sv[n * 4 + 1];
            ps1 += Sv[n * 4 + 2] + Sv[n * 4 + 3];
        }
        ps0 += __shfl_xor_sync(0xffffffffu, ps0, 1);
        ps0 += __shfl_xor_sync(0xffffffffu, ps0, 2);
        ps1 += __shfl_xor_sync(0xffffffffu, ps1, 1);
        ps1 += __shfl_xor_sync(0xffffffffu, ps1, 2);

        l0 = l0 * a0 + ps0;  m0 = m0n;
        l1 = l1 * a1 + ps1;  m1 = m1n;
        #pragma unroll
        for (int n = 0; n < 8; n++) {
            O[n * 4 + 0] *= a0;  O[n * 4 + 1] *= a0;
            O[n * 4 + 2] *= a1;  O[n * 4 + 3] *= a1;
        }

        // ---- P fragments (C-layout == A-layout) ----
        uint32_t Ph[4][4], Pl[4][4];
        #pragma unroll
        for (int ks = 0; ks < 4; ks++) {
            bsplit2(Sv[(2*ks)   * 4 + 0], Sv[(2*ks)   * 4 + 1], Ph[ks][0], Pl[ks][0]);
            bsplit2(Sv[(2*ks)   * 4 + 2], Sv[(2*ks)   * 4 + 3], Ph[ks][1], Pl[ks][1]);
            bsplit2(Sv[(2*ks+1) * 4 + 0], Sv[(2*ks+1) * 4 + 1], Ph[ks][2], Pl[ks][2]);
            bsplit2(Sv[(2*ks+1) * 4 + 2], Sv[(2*ks+1) * 4 + 3], Ph[ks][3], Pl[ks][3]);
        }

        // ---- O += P @ V ----
        #pragma unroll
        for (int ks = 0; ks < 4; ks++) {
            #pragma unroll
            for (int np = 0; np < 4; np++) {
                int ntile = np * 2 + (lane >> 4);
                int row   = ntile * 8 + (lane & 7);       // channel row
                int colw  = ks * 8 + ((lane >> 3) & 1) * 4; // keypair word
                uint32_t off = (uint32_t)(row * 36 + colw) * 4;
                uint32_t vh0, vh1, vh2, vh3, vl0, vl1, vl2, vl3;
                ldsm4(vbase + off,            vh0, vh1, vh2, vh3);
                ldsm4(vbase + off + 2304 * 4, vl0, vl1, vl2, vl3);
                float* d0 = &O[(np * 2) * 4];
                float* d1 = &O[(np * 2 + 1) * 4];
                mma_bf16(d0, Ph[ks], vh0, vh1);
                mma_bf16(d0, Ph[ks], vl0, vl1);
                mma_bf16(d0, Pl[ks], vh0, vh1);
                mma_bf16(d1, Ph[ks], vh2, vh3);
                mma_bf16(d1, Ph[ks], vl2, vl3);
                mma_bf16(d1, Pl[ks], vh2, vh3);
            }
        }
        __syncthreads();

        // prefetch chunk kt+2 into the buffer just consumed
        if (kt + 2 < 64) {
            int c = kt + 2;
            attn_issue(sbytes, bufw, t,
                       Kh + (size_t)c * 64 * 32, Kl + (size_t)c * 64 * 32,
                       Vh + c * 32,              Vl + c * 32);
        }
    }

    float inv0 = 1.0f / l0, inv1 = 1.0f / l1;
    float* Og = g_O + ((size_t)b * HW_ + qt * 128 + w * 16) * C_;
    #pragma unroll
    for (int n = 0; n < 8; n++) {
        int col = n * 8 + 2 * tg;
        *(float2*)&Og[g * 64 + col]       = make_float2(O[n*4+0] * inv0, O[n*4+1] * inv0);
        *(float2*)&Og[(g + 8) * 64 + col] = make_float2(O[n*4+2] * inv1, O[n*4+3] * inv1);
    }
}

// ---------------------------------------------------------------------------
// Kernel 3: mixed = relu(O @ wm^T + bm) via tensor cores + 2x2 avg pool.
// (unchanged from R5 — known good)
// ---------------------------------------------------------------------------
#define MX_WHI 0
#define MX_WLO 2304
#define MX_MS  4608
#define MX_WORDS (4608 + 128 * 68)        // 13312 words = 53248 B

__global__ __launch_bounds__(256, 2) void mixpool_kernel(
    const float* __restrict__ wm,
    const float* __restrict__ bm,
    float* __restrict__ out)
{
    extern __shared__ uint32_t sw[];
    float* ms = (float*)&sw[MX_MS];

    const int b    = blockIdx.y;
    const int oy   = blockIdx.x;
    const int t    = threadIdx.x;
    const int w    = t >> 5;
    const int lane = t & 31;
    const int g    = lane >> 2;
    const int tg   = lane & 3;

    #pragma unroll
    for (int i = 0; i < 8; i++) {
        int idx = t + i * 256;
        int d = idx >> 5, cp = idx & 31;
        float2 wv2 = *(const float2*)&wm[d * 64 + 2 * cp];
        uint32_t h, l;
        bsplit2(wv2.x, wv2.y, h, l);
        sw[MX_WHI + d * 36 + cp] = h;
        sw[MX_WLO + d * 36 + cp] = l;
    }

    uint32_t Ahi[4][4], Alo[4][4];
    {
        const float* Og = g_O + ((size_t)b * HW_ + oy * 128 + w * 16) * C_;
        #pragma unroll
        for (int ks = 0; ks < 4; ks++) {
            int cb = ks * 16 + 2 * tg;
            float2 q00 = *(const float2*)&Og[g * 64 + cb];
            float2 q10 = *(const float2*)&Og[(g + 8) * 64 + cb];
            float2 q01 = *(const float2*)&Og[g * 64 + cb + 8];
            float2 q11 = *(const float2*)&Og[(g + 8) * 64 + cb + 8];
            bsplit2(q00.x, q00.y, Ahi[ks][0], Alo[ks][0]);
            bsplit2(q10.x, q10.y, Ahi[ks][1], Alo[ks][1]);
            bsplit2(q01.x, q01.y, Ahi[ks][2], Alo[ks][2]);
            bsplit2(q11.x, q11.y, Ahi[ks][3], Alo[ks][3]);
        }
    }
    __syncthreads();

    float acc[32];
    #pragma unroll
    for (int n = 0; n < 8; n++) {
        float b0 = bm[n * 8 + 2 * tg];
        float b1 = bm[n * 8 + 2 * tg + 1];
        acc[n * 4 + 0] = b0; acc[n * 4 + 1] = b1;
        acc[n * 4 + 2] = b0; acc[n * 4 + 3] = b1;
    }
    #pragma unroll
    for (int ks = 0; ks < 4; ks++) {
        #pragma unroll
        for (int n = 0; n < 8; n++) {
            uint32_t base = (uint32_t)(n * 8 + g) * 36 + tg + ks * 8;
            uint32_t bh0 = sw[MX_WHI + base];
            uint32_t bh1 = sw[MX_WHI + base + 4];
            uint32_t bl0 = sw[MX_WLO + base];
            uint32_t bl1 = sw[MX_WLO + base + 4];
            float* d = &acc[n * 4];
            mma_bf16(d, Ahi[ks], bh0, bh1);
            mma_bf16(d, Ahi[ks], bl0, bl1);
            mma_bf16(d, Alo[ks], bh0, bh1);
        }
    }

    {
        int r0 = w * 16 + g, r1 = r0 + 8;
        #pragma unroll
        for (int n = 0; n < 8; n++) {
            int col = n * 8 + 2 * tg;
            *(float2*)&ms[r0 * 68 + col] =
                make_float2(fmaxf(acc[n*4+0], 0.0f), fmaxf(acc[n*4+1], 0.0f));
            *(float2*)&ms[r1 * 68 + col] =
                make_float2(fmaxf(acc[n*4+2], 0.0f), fmaxf(acc[n*4+3], 0.0f));
        }
    }
    __syncthreads();

    #pragma unroll
    for (int k = 0; k < 8; k++) {
        int oidx = t + k * 256;
        int ch = oidx >> 5, ox = oidx & 31;
        float s = ms[(2 * ox)      * 68 + ch]
                + ms[(2 * ox + 1)  * 68 + ch]
                + ms[(64 + 2 * ox) * 68 + ch]
                + ms[(65 + 2 * ox) * 68 + ch];
        out[(((size_t)b * C_ + ch) * 32 + oy) * 32 + ox] = 0.25f * s;
    }
}

// ---------------------------------------------------------------------------
extern "C" void kernel_launch(void* const* d_in, const int* in_sizes, int n_in,
                              void* d_out, int out_size)
{
    const float* x  = (const float*)d_in[0];
    const float* wq = (const float*)d_in[1];
    const float* bq = (const float*)d_in[2];
    const float* wk = (const float*)d_in[3];
    const float* bk = (const float*)d_in[4];
    const float* wv = (const float*)d_in[5];
    const float* bv = (const float*)d_in[6];
    const float* wm = (const float*)d_in[7];
    const float* bm = (const float*)d_in[8];
    float* out = (float*)d_out;

    const int smem_proj = PJ_WORDS * sizeof(uint32_t);   // 92160
    const int smem_attn = AB_WORDS * sizeof(uint32_t);   // 73728
    const int smem_mix  = MX_WORDS * sizeof(uint32_t);   // 53248

    cudaFuncSetAttribute(proj_kernel,    cudaFuncAttributeMaxDynamicSharedMemorySize, smem_proj);
    cudaFuncSetAttribute(attn_kernel,    cudaFuncAttributeMaxDynamicSharedMemorySize, smem_attn);
    cudaFuncSetAttribute(mixpool_kernel, cudaFuncAttributeMaxDynamicSharedMemorySize, smem_mix);

    proj_kernel<<<dim3(32, B_), 256, smem_proj>>>(x, wq, bq, wk, bk, wv, bv);
    vconv_kernel<<<dim3(64, B_), 256>>>();
    attn_kernel<<<dim3(32, B_), 256, smem_attn>>>();
    mixpool_kernel<<<dim3(32, B_), 256, smem_mix>>>(wm, bm, out);
}